// round 13
// baseline (speedup 1.0000x reference)
#include <cuda_runtime.h>

// CorrAttentionBias: out[b,h,i,j] = attn + alpha*edge + beta*cs_i*cs_j, masked to NEG.
// B=2, H=16, L=2048. DRAM-roofline-bound streaming kernel — CONVERGED FINAL.
//
// Session design-matrix (kernel us / DRAM%):
//   256t x 2f4 default policy (this): 117.0 / 81.2   <-- optimum, 3x reproduced
//   256t x 2f4 + __ldcs/__stcs:      119.6 / 79.4   (hints mildly negative)
//   256-bit aggregates:               117.7 / 80.7
//   2-row paired:                     117.2 / 81.0   (regs 40, occ 60)
//   128t x 4f4:                       123.6 / 76.7   (occ 63)
//   512t x 1f4:                       152.4 / 62.5   (MLP 1 exposes latency)
//   persistent grid-stride:           138.6 / 68.7   (loop-carried row dependency)
// Traffic model: 537MB write + ~268MB mask-skipped read = 750MB @ 6.4TB/s = 117us.
// Mask dtype is int32 (proven on this dataset).

#define ALPHA 0.5f
#define BETA  0.1f
#define NEGV  -100000.0f

namespace {
constexpr int B = 2;
constexpr int H = 16;
constexpr int L = 2048;
constexpr int THREADS = 256;
constexpr int V4_PER_THREAD = (L / 4) / THREADS;  // 2
}

__global__ __launch_bounds__(THREADS) void corr_bias_kernel(
    const float* __restrict__ attn,
    const float* __restrict__ c_local,
    const float* __restrict__ c_sink,
    const int* __restrict__ mask,     // int32 per element
    float* __restrict__ out)
{
    const unsigned r = blockIdx.x;            // r = (b*H + h)*L + i
    const int i = r & (L - 1);
    const int b = r >> 15;                    // H*L = 32768
    const long long base = (long long)r * L;

    float4* __restrict__ o4 = reinterpret_cast<float4*>(out + base);

    // Fully-masked row: write-only fast path (saves ~50% of attn reads).
    if (mask[b * L + i]) {
        const float4 neg = make_float4(NEGV, NEGV, NEGV, NEGV);
        #pragma unroll
        for (int k = 0; k < V4_PER_THREAD; k++)
            o4[threadIdx.x + k * THREADS] = neg;
        return;
    }

    const float4* __restrict__ a4  = reinterpret_cast<const float4*>(attn + base);
    const float4* __restrict__ cs4 = reinterpret_cast<const float4*>(c_sink + b * L);
    const int4*   __restrict__ mi4 = reinterpret_cast<const int4*>(mask + b * L);

    const float csi = BETA * c_sink[b * L + i];

    // Neighbor bias values, matching the reference's overwrite semantics:
    //   j = i+1 : alpha * c_local[b, i+1]                     (i <= L-2)
    //   j = i-1 : alpha * c_local[b, i-1]  if 2 <= i <= L-2
    //             alpha * c_local[b, i]    if i == 1 or i == L-1
    float nl = 0.f, nr = 0.f;
    if (i >= 1) {
        nl = (i >= 2 && i <= L - 2) ? ALPHA * c_local[b * L + i - 1]
                                    : ALPHA * c_local[b * L + i];
    }
    if (i <= L - 2) {
        nr = ALPHA * c_local[b * L + i + 1];
    }

    #pragma unroll
    for (int k = 0; k < V4_PER_THREAD; k++) {
        const int v = threadIdx.x + k * THREADS;  // float4 index within row
        const int j = v * 4;

        const float4 a  = a4[v];
        const float4 cs = cs4[v];
        const int4   m  = mi4[v];

        float o0 = fmaf(csi, cs.x, a.x);
        float o1 = fmaf(csi, cs.y, a.y);
        float o2 = fmaf(csi, cs.z, a.z);
        float o3 = fmaf(csi, cs.w, a.w);

        // neighbor diagonals (at most one lane per vector hits)
        if (j - 3 <= i + 1 && i - 1 <= j + 3) {
            if (j + 0 == i - 1) o0 += nl; else if (j + 0 == i + 1) o0 += nr;
            if (j + 1 == i - 1) o1 += nl; else if (j + 1 == i + 1) o1 += nr;
            if (j + 2 == i - 1) o2 += nl; else if (j + 2 == i + 1) o2 += nr;
            if (j + 3 == i - 1) o3 += nl; else if (j + 3 == i + 1) o3 += nr;
        }

        if (m.x) o0 = NEGV;
        if (m.y) o1 = NEGV;
        if (m.z) o2 = NEGV;
        if (m.w) o3 = NEGV;

        o4[v] = make_float4(o0, o1, o2, o3);
    }
}

extern "C" void kernel_launch(void* const* d_in, const int* in_sizes, int n_in,
                              void* d_out, int out_size)
{
    const float* attn    = (const float*)d_in[0];
    const float* c_local = (const float*)d_in[1];
    const float* c_sink  = (const float*)d_in[2];
    const int*   mask    = (const int*)d_in[3];
    float*       out     = (float*)d_out;

    const int grid = B * H * L;  // 65536 row-blocks
    corr_bias_kernel<<<grid, THREADS>>>(attn, c_local, c_sink, mask, out);
}

// round 14
// speedup vs baseline: 1.0008x; 1.0008x over previous
#include <cuda_runtime.h>

// CorrAttentionBias: out[b,h,i,j] = attn + alpha*edge + beta*cs_i*cs_j, masked to NEG.
// B=2, H=16, L=2048. DRAM-roofline-bound. Two-phase probe: separate the
// 1:1 read:write stream (unmasked rows) from the pure-write stream (masked rows)
// into sequential launches to eliminate HBM read/write bus-turnaround mixing.
// Each phase early-exits on the row-mask bit (L2-hot scalar) for non-owned rows.
// Mask dtype is int32 (proven on this dataset).

#define ALPHA 0.5f
#define BETA  0.1f
#define NEGV  -100000.0f

namespace {
constexpr int B = 2;
constexpr int H = 16;
constexpr int L = 2048;
constexpr int THREADS = 256;
constexpr int V4_PER_THREAD = (L / 4) / THREADS;  // 2
}

// Phase 1: unmasked rows only — 1:1 read:write alternating stream.
__global__ __launch_bounds__(THREADS) void corr_bias_compute_kernel(
    const float* __restrict__ attn,
    const float* __restrict__ c_local,
    const float* __restrict__ c_sink,
    const int* __restrict__ mask,
    float* __restrict__ out)
{
    const unsigned r = blockIdx.x;            // r = (b*H + h)*L + i
    const int i = r & (L - 1);
    const int b = r >> 15;                    // H*L = 32768

    if (mask[b * L + i]) return;              // masked rows handled in phase 2

    const long long base = (long long)r * L;
    float4* __restrict__ o4 = reinterpret_cast<float4*>(out + base);
    const float4* __restrict__ a4  = reinterpret_cast<const float4*>(attn + base);
    const float4* __restrict__ cs4 = reinterpret_cast<const float4*>(c_sink + b * L);
    const int4*   __restrict__ mi4 = reinterpret_cast<const int4*>(mask + b * L);

    const float csi = BETA * c_sink[b * L + i];

    // Neighbor bias values, matching the reference's overwrite semantics:
    //   j = i+1 : alpha * c_local[b, i+1]                     (i <= L-2)
    //   j = i-1 : alpha * c_local[b, i-1]  if 2 <= i <= L-2
    //             alpha * c_local[b, i]    if i == 1 or i == L-1
    float nl = 0.f, nr = 0.f;
    if (i >= 1) {
        nl = (i >= 2 && i <= L - 2) ? ALPHA * c_local[b * L + i - 1]
                                    : ALPHA * c_local[b * L + i];
    }
    if (i <= L - 2) {
        nr = ALPHA * c_local[b * L + i + 1];
    }

    #pragma unroll
    for (int k = 0; k < V4_PER_THREAD; k++) {
        const int v = threadIdx.x + k * THREADS;  // float4 index within row
        const int j = v * 4;

        const float4 a  = a4[v];
        const float4 cs = cs4[v];
        const int4   m  = mi4[v];

        float o0 = fmaf(csi, cs.x, a.x);
        float o1 = fmaf(csi, cs.y, a.y);
        float o2 = fmaf(csi, cs.z, a.z);
        float o3 = fmaf(csi, cs.w, a.w);

        // neighbor diagonals (at most one lane per vector hits)
        if (j - 3 <= i + 1 && i - 1 <= j + 3) {
            if (j + 0 == i - 1) o0 += nl; else if (j + 0 == i + 1) o0 += nr;
            if (j + 1 == i - 1) o1 += nl; else if (j + 1 == i + 1) o1 += nr;
            if (j + 2 == i - 1) o2 += nl; else if (j + 2 == i + 1) o2 += nr;
            if (j + 3 == i - 1) o3 += nl; else if (j + 3 == i + 1) o3 += nr;
        }

        if (m.x) o0 = NEGV;
        if (m.y) o1 = NEGV;
        if (m.z) o2 = NEGV;
        if (m.w) o3 = NEGV;

        o4[v] = make_float4(o0, o1, o2, o3);
    }
}

// Phase 2: masked rows only — pure write burst.
__global__ __launch_bounds__(THREADS) void corr_bias_maskfill_kernel(
    const int* __restrict__ mask,
    float* __restrict__ out)
{
    const unsigned r = blockIdx.x;
    const int i = r & (L - 1);
    const int b = r >> 15;

    if (!mask[b * L + i]) return;             // unmasked rows done in phase 1

    const long long base = (long long)r * L;
    float4* __restrict__ o4 = reinterpret_cast<float4*>(out + base);
    const float4 neg = make_float4(NEGV, NEGV, NEGV, NEGV);
    #pragma unroll
    for (int k = 0; k < V4_PER_THREAD; k++)
        o4[threadIdx.x + k * THREADS] = neg;
}

extern "C" void kernel_launch(void* const* d_in, const int* in_sizes, int n_in,
                              void* d_out, int out_size)
{
    const float* attn    = (const float*)d_in[0];
    const float* c_local = (const float*)d_in[1];
    const float* c_sink  = (const float*)d_in[2];
    const int*   mask    = (const int*)d_in[3];
    float*       out     = (float*)d_out;

    const int grid = B * H * L;  // 65536 row-blocks per phase
    corr_bias_compute_kernel<<<grid, THREADS>>>(attn, c_local, c_sink, mask, out);
    corr_bias_maskfill_kernel<<<grid, THREADS>>>(mask, out);
}

// round 15
// speedup vs baseline: 1.0036x; 1.0029x over previous
#include <cuda_runtime.h>

// CorrAttentionBias: out[b,h,i,j] = attn + alpha*edge + beta*cs_i*cs_j, masked to NEG.
// B=2, H=16, L=2048. Two-phase split (measured: separating streams lifts the
// mixed read/write phase to ~87% DRAM vs 81% fused).
//   Phase 1: unmasked rows, 1:1 read:write stream (unchanged, ~87% DRAM).
//   Phase 2: masked rows, pure write burst — 8 rows/CTA with front-batched
//            broadcast mask loads (2x int4) so stores issue back-to-back,
//            fixing R14's latency-gated 63%-DRAM write phase.
// Mask dtype is int32 (proven on this dataset).

#define ALPHA 0.5f
#define BETA  0.1f
#define NEGV  -100000.0f

namespace {
constexpr int B = 2;
constexpr int H = 16;
constexpr int L = 2048;
constexpr int THREADS = 256;
constexpr int V4_PER_THREAD = (L / 4) / THREADS;  // 2
constexpr int NROWS = B * H * L;                  // 65536
constexpr int ROWS_PER_FILL_CTA = 8;
}

// Phase 1: unmasked rows only — 1:1 read:write alternating stream.
__global__ __launch_bounds__(THREADS) void corr_bias_compute_kernel(
    const float* __restrict__ attn,
    const float* __restrict__ c_local,
    const float* __restrict__ c_sink,
    const int* __restrict__ mask,
    float* __restrict__ out)
{
    const unsigned r = blockIdx.x;            // r = (b*H + h)*L + i
    const int i = r & (L - 1);
    const int b = r >> 15;                    // H*L = 32768

    if (mask[b * L + i]) return;              // masked rows handled in phase 2

    const long long base = (long long)r * L;
    float4* __restrict__ o4 = reinterpret_cast<float4*>(out + base);
    const float4* __restrict__ a4  = reinterpret_cast<const float4*>(attn + base);
    const float4* __restrict__ cs4 = reinterpret_cast<const float4*>(c_sink + b * L);
    const int4*   __restrict__ mi4 = reinterpret_cast<const int4*>(mask + b * L);

    const float csi = BETA * c_sink[b * L + i];

    // Neighbor bias values, matching the reference's overwrite semantics:
    //   j = i+1 : alpha * c_local[b, i+1]                     (i <= L-2)
    //   j = i-1 : alpha * c_local[b, i-1]  if 2 <= i <= L-2
    //             alpha * c_local[b, i]    if i == 1 or i == L-1
    float nl = 0.f, nr = 0.f;
    if (i >= 1) {
        nl = (i >= 2 && i <= L - 2) ? ALPHA * c_local[b * L + i - 1]
                                    : ALPHA * c_local[b * L + i];
    }
    if (i <= L - 2) {
        nr = ALPHA * c_local[b * L + i + 1];
    }

    #pragma unroll
    for (int k = 0; k < V4_PER_THREAD; k++) {
        const int v = threadIdx.x + k * THREADS;  // float4 index within row
        const int j = v * 4;

        const float4 a  = a4[v];
        const float4 cs = cs4[v];
        const int4   m  = mi4[v];

        float o0 = fmaf(csi, cs.x, a.x);
        float o1 = fmaf(csi, cs.y, a.y);
        float o2 = fmaf(csi, cs.z, a.z);
        float o3 = fmaf(csi, cs.w, a.w);

        // neighbor diagonals (at most one lane per vector hits)
        if (j - 3 <= i + 1 && i - 1 <= j + 3) {
            if (j + 0 == i - 1) o0 += nl; else if (j + 0 == i + 1) o0 += nr;
            if (j + 1 == i - 1) o1 += nl; else if (j + 1 == i + 1) o1 += nr;
            if (j + 2 == i - 1) o2 += nl; else if (j + 2 == i + 1) o2 += nr;
            if (j + 3 == i - 1) o3 += nl; else if (j + 3 == i + 1) o3 += nr;
        }

        if (m.x) o0 = NEGV;
        if (m.y) o1 = NEGV;
        if (m.z) o2 = NEGV;
        if (m.w) o3 = NEGV;

        o4[v] = make_float4(o0, o1, o2, o3);
    }
}

// Phase 2: masked rows only — pure write burst, 8 rows per CTA.
// Row block r0..r0+7 never crosses a batch boundary (32768 % 8 == 0), and the
// 8 row indices i0..i0+7 are contiguous, so the 8 masks are 2 aligned int4s.
__global__ __launch_bounds__(THREADS) void corr_bias_maskfill_kernel(
    const int* __restrict__ mask,
    float* __restrict__ out)
{
    const unsigned r0 = blockIdx.x * ROWS_PER_FILL_CTA;
    const int i0 = r0 & (L - 1);              // L % 8 == 0 -> i0..i0+7 in-row
    const int b  = r0 >> 15;

    // Front-batched broadcast mask loads: two independent int4s, no per-row stall.
    const int4* __restrict__ mrow = reinterpret_cast<const int4*>(mask + b * L + i0);
    const int4 mA = mrow[0];
    const int4 mB = mrow[1];
    const int mk[ROWS_PER_FILL_CTA] = { mA.x, mA.y, mA.z, mA.w,
                                        mB.x, mB.y, mB.z, mB.w };

    const float4 neg = make_float4(NEGV, NEGV, NEGV, NEGV);
    const int t = threadIdx.x;

    #pragma unroll
    for (int k = 0; k < ROWS_PER_FILL_CTA; k++) {
        if (mk[k]) {                          // block-uniform branch
            float4* __restrict__ o4 =
                reinterpret_cast<float4*>(out + (long long)(r0 + k) * L);
            #pragma unroll
            for (int q = 0; q < V4_PER_THREAD; q++)
                o4[t + q * THREADS] = neg;
        }
    }
}

extern "C" void kernel_launch(void* const* d_in, const int* in_sizes, int n_in,
                              void* d_out, int out_size)
{
    const float* attn    = (const float*)d_in[0];
    const float* c_local = (const float*)d_in[1];
    const float* c_sink  = (const float*)d_in[2];
    const int*   mask    = (const int*)d_in[3];
    float*       out     = (float*)d_out;

    corr_bias_compute_kernel<<<NROWS, THREADS>>>(attn, c_local, c_sink, mask, out);
    corr_bias_maskfill_kernel<<<NROWS / ROWS_PER_FILL_CTA, THREADS>>>(mask, out);
}